// round 2
// baseline (speedup 1.0000x reference)
#include <cuda_runtime.h>

// Problem constants
#define F_DENSE  13
#define F_SPARSE 26
#define NF       39          // F_DENSE + F_SPARSE
#define E_DIM    16
#define VOC      100000
#define H1       512
#define H2       256
#define D_IN     624         // (13+26)*16

#define SMP_PER_BLOCK 32     // 128 threads, 4 warps x 8 samples
#define THREADS       128

// Scratch (device globals; no allocation allowed)
__device__ float g_w2eff[H1];
__device__ __align__(16) float g_w1eff[D_IN];
__device__ float g_CONST;

// ---------------------------------------------------------------------------
// Prep 1: w2eff[k] = sum_j Lw2[k,j] * g2[j]
// ---------------------------------------------------------------------------
__global__ void prep_w2eff(const float* __restrict__ Lw2,
                           const float* __restrict__ g2) {
    int w    = (blockIdx.x * blockDim.x + threadIdx.x) >> 5;
    int lane = threadIdx.x & 31;
    if (w >= H1) return;
    float acc = 0.f;
#pragma unroll
    for (int i = 0; i < H2 / 32; i++) {
        int j = lane + i * 32;
        acc = fmaf(__ldg(Lw2 + w * H2 + j), __ldg(g2 + j), acc);
    }
#pragma unroll
    for (int o = 16; o; o >>= 1) acc += __shfl_xor_sync(0xffffffffu, acc, o);
    if (lane == 0) g_w2eff[w] = acc;
}

// ---------------------------------------------------------------------------
// Prep 2: scalar constant
// ---------------------------------------------------------------------------
__global__ void prep_const(const float* __restrict__ Lb1,
                           const float* __restrict__ g1,
                           const float* __restrict__ be1,
                           const float* __restrict__ Lb2,
                           const float* __restrict__ g2,
                           const float* __restrict__ be2) {
    const float inv = rsqrtf(1.f + 1e-5f);
    int k = threadIdx.x;
    float w2e = g_w2eff[k];
    float v = inv * inv * g1[k] * w2e * Lb1[k] + inv * be1[k] * w2e;
    if (k < H2) v += inv * g2[k] * Lb2[k] + be2[k];
    __shared__ float sh[H1];
    sh[k] = v;
    __syncthreads();
    for (int s = H1 / 2; s; s >>= 1) {
        if (k < s) sh[k] += sh[k + s];
        __syncthreads();
    }
    if (k == 0) g_CONST = sh[0];
}

// ---------------------------------------------------------------------------
// Prep 3: w1eff[d] = sum_k Lw1[d,k] * g1[k] * w2eff[k]
// ---------------------------------------------------------------------------
__global__ void prep_w1eff(const float* __restrict__ Lw1,
                           const float* __restrict__ g1) {
    int w    = (blockIdx.x * blockDim.x + threadIdx.x) >> 5;
    int lane = threadIdx.x & 31;
    if (w >= D_IN) return;
    float acc = 0.f;
#pragma unroll
    for (int i = 0; i < H1 / 32; i++) {
        int k = lane + i * 32;
        acc = fmaf(__ldg(Lw1 + w * H1 + k), __ldg(g1 + k) * g_w2eff[k], acc);
    }
#pragma unroll
    for (int o = 16; o; o >>= 1) acc += __shfl_xor_sync(0xffffffffu, acc, o);
    if (lane == 0) g_w1eff[w] = acc;
}

// ---------------------------------------------------------------------------
// Helpers
// ---------------------------------------------------------------------------
__device__ __forceinline__ float dot4(float4 a, float4 b) {
    return a.x * b.x + a.y * b.y + a.z * b.z + a.w * b.w;
}

// Process CH sparse slots starting at slot c0 for this lane's sample.
template <int CH>
__device__ __forceinline__ void sparse_chunk(
    int c0,
    const int*   s_xi,          // this sample's 39 indices (smem)
    const float* s_xv,          // this sample's 39 values  (smem)
    int q,                      // quad within row (0..3) -> e = 4q..4q+3
    const float4* __restrict__ emb1_4,
    const float4* __restrict__ emb2_4,
    const float4* w1e4,
    float&  fm1, float4& se, float& ss, float& hd)
{
    float4 A1[CH], A2[CH];
    float  vv[CH];
    int    row4[CH];
#pragma unroll
    for (int j = 0; j < CH; j++) {
        int s   = c0 + j;
        int idx = s_xi[F_DENSE + s];
        vv[j]   = s_xv[F_DENSE + s];
        row4[j] = (s * VOC + idx) * 4 + q;     // float4 index
    }
    // Issue all loads for the chunk (16 LDG.128 in flight)
#pragma unroll
    for (int j = 0; j < CH; j++) A1[j] = __ldg(emb1_4 + row4[j]);
#pragma unroll
    for (int j = 0; j < CH; j++) A2[j] = __ldg(emb2_4 + row4[j]);
    // Consume
#pragma unroll
    for (int j = 0; j < CH; j++) {
        int s = c0 + j;
        float v = vv[j];
        fm1 = fmaf(v, A1[j].x + A1[j].y + A1[j].z + A1[j].w, fm1);
        float4 sev = make_float4(A2[j].x * v, A2[j].y * v, A2[j].z * v, A2[j].w * v);
        se.x += sev.x; se.y += sev.y; se.z += sev.z; se.w += sev.w;
        ss  = fmaf(sev.x, sev.x, fmaf(sev.y, sev.y, fmaf(sev.z, sev.z, fmaf(sev.w, sev.w, ss))));
        float4 w = w1e4[(F_DENSE + s) * 4 + q];
        hd += dot4(sev, w);
    }
}

// ---------------------------------------------------------------------------
// Main kernel: 4 lanes per sample (lane-quad = 4 embedding columns via float4),
// 8 samples per warp, 128 threads => 32 samples/block.
// ---------------------------------------------------------------------------
__global__ __launch_bounds__(THREADS) void deepfm_main(
    const int*   __restrict__ Xi,
    const float* __restrict__ Xv,
    const float* __restrict__ W1,
    const float* __restrict__ b1,
    const float* __restrict__ emb1,
    const float* __restrict__ W2,
    const float* __restrict__ b2,
    const float* __restrict__ emb2,
    const float* __restrict__ bias,
    float*       __restrict__ out,
    int n) {
    const float inv2 = 1.f / (1.f + 1e-5f);   // inv^2 = 1/(1+eps)

    __shared__ int   sh_xi[SMP_PER_BLOCK * NF];
    __shared__ float sh_xv[SMP_PER_BLOCK * NF];

    int tid   = threadIdx.x;
    int base  = blockIdx.x * SMP_PER_BLOCK;

    // Coalesced staging of Xi / Xv tiles
    int tile = SMP_PER_BLOCK * NF;
    int gmax = n * NF - base * NF;
    for (int i = tid; i < tile; i += THREADS) {
        if (i < gmax) {
            sh_xi[i] = Xi[base * NF + i];
            sh_xv[i] = Xv[base * NF + i];
        }
    }
    __syncthreads();

    int lane = tid & 31;
    int q    = lane & 3;          // float4 quadrant within 64B row
    int sub  = lane >> 2;         // sample within warp (0..7)
    int warp = tid >> 5;
    int smp  = warp * 8 + sub;    // sample within block
    int b    = base + smp;
    if (b >= n) return;

    const int*   xi = sh_xi + smp * NF;
    const float* xv = sh_xv + smp * NF;

    const float4* emb1_4 = (const float4*)emb1;
    const float4* emb2_4 = (const float4*)emb2;
    const float4* W1_4   = (const float4*)W1;
    const float4* b1_4   = (const float4*)b1;
    const float4* W2_4   = (const float4*)W2;
    const float4* b2_4   = (const float4*)b2;
    const float4* w1e4   = (const float4*)g_w1eff;

    float  fm1 = 0.f;
    float4 se  = make_float4(0.f, 0.f, 0.f, 0.f);
    float  ss  = 0.f;
    float  hd  = 0.f;

    // Sparse gathers first (the DRAM-bound part), batched for MLP
    sparse_chunk<8>( 0, xi, xv, q, emb1_4, emb2_4, w1e4, fm1, se, ss, hd);
    sparse_chunk<8>( 8, xi, xv, q, emb1_4, emb2_4, w1e4, fm1, se, ss, hd);
    sparse_chunk<8>(16, xi, xv, q, emb1_4, emb2_4, w1e4, fm1, se, ss, hd);
    sparse_chunk<2>(24, xi, xv, q, emb1_4, emb2_4, w1e4, fm1, se, ss, hd);

    // Dense features (all params L1/L2-resident)
#pragma unroll
    for (int f = 0; f < F_DENSE; f++) {
        float x = (float)xi[f];
        float v = xv[f];
        int   o = f * 4 + q;
        float4 w2 = __ldg(W2_4 + o);
        float4 bb2 = __ldg(b2_4 + o);
        float4 sl = make_float4(fmaf(x, w2.x, bb2.x), fmaf(x, w2.y, bb2.y),
                                fmaf(x, w2.z, bb2.z), fmaf(x, w2.w, bb2.w));
        float4 w1 = __ldg(W1_4 + o);
        float4 bb1 = __ldg(b1_4 + o);
        float fl = fmaf(x, w1.x, bb1.x) + fmaf(x, w1.y, bb1.y)
                 + fmaf(x, w1.z, bb1.z) + fmaf(x, w1.w, bb1.w);
        fm1 = fmaf(fl, v, fm1);
        se.x += sl.x; se.y += sl.y; se.z += sl.z; se.w += sl.w;
        ss  = fmaf(sl.x, sl.x, fmaf(sl.y, sl.y, fmaf(sl.z, sl.z, fmaf(sl.w, sl.w, ss))));
        hd += dot4(sl, w1e4[o]);
    }

    // Per-lane partial; fm_second per-e is exact (each e owned by one lane)
    float r = fm1 + 0.5f * (dot4(se, se) - ss) + inv2 * hd;

    // Fold the 4 lanes of this sample
    r += __shfl_xor_sync(0xffffffffu, r, 1);
    r += __shfl_xor_sync(0xffffffffu, r, 2);

    if (q == 0) out[b] = r + g_CONST + __ldg(bias + b);
}

// ---------------------------------------------------------------------------
extern "C" void kernel_launch(void* const* d_in, const int* in_sizes, int n_in,
                              void* d_out, int out_size) {
    const int*   Xi   = (const int*)  d_in[0];
    const float* Xv   = (const float*)d_in[1];
    const float* W1   = (const float*)d_in[2];
    const float* b1   = (const float*)d_in[3];
    const float* emb1 = (const float*)d_in[4];
    const float* W2   = (const float*)d_in[5];
    const float* b2   = (const float*)d_in[6];
    const float* emb2 = (const float*)d_in[7];
    const float* Lw1  = (const float*)d_in[8];
    const float* Lb1  = (const float*)d_in[9];
    const float* g1   = (const float*)d_in[10];
    const float* be1  = (const float*)d_in[11];
    const float* Lw2  = (const float*)d_in[12];
    const float* Lb2  = (const float*)d_in[13];
    const float* g2   = (const float*)d_in[14];
    const float* be2  = (const float*)d_in[15];
    const float* bias = (const float*)d_in[16];
    float* out = (float*)d_out;

    prep_w2eff<<<(H1 * 32 + 255) / 256, 256>>>(Lw2, g2);
    prep_const<<<1, H1>>>(Lb1, g1, be1, Lb2, g2, be2);
    prep_w1eff<<<(D_IN * 32 + 255) / 256, 256>>>(Lw1, g1);

    int n = out_size;
    int blocks = (n + SMP_PER_BLOCK - 1) / SMP_PER_BLOCK;
    deepfm_main<<<blocks, THREADS>>>(Xi, Xv, W1, b1, emb1, W2, b2, emb2,
                                     bias, out, n);
}

// round 3
// speedup vs baseline: 1.2590x; 1.2590x over previous
#include <cuda_runtime.h>

// Problem constants
#define F_DENSE  13
#define F_SPARSE 26
#define NF       39          // F_DENSE + F_SPARSE
#define E_DIM    16
#define VOC      100000
#define H1       512
#define H2       256
#define D_IN     624         // (13+26)*16

#define SMP_PER_BLOCK 8      // 1 warp per sample, 256 threads = 8 warps
#define THREADS       256

// Scratch (device globals; no allocation allowed)
__device__ float g_w2eff[H1];
__device__ float g_w1eff[D_IN];
__device__ float g_CONST;

// ---------------------------------------------------------------------------
// Prep 1: w2eff[k] = sum_j Lw2[k,j] * g2[j]
// ---------------------------------------------------------------------------
__global__ void prep_w2eff(const float* __restrict__ Lw2,
                           const float* __restrict__ g2) {
    int w    = (blockIdx.x * blockDim.x + threadIdx.x) >> 5;
    int lane = threadIdx.x & 31;
    if (w >= H1) return;
    float acc = 0.f;
#pragma unroll
    for (int i = 0; i < H2 / 32; i++) {
        int j = lane + i * 32;
        acc = fmaf(__ldg(Lw2 + w * H2 + j), __ldg(g2 + j), acc);
    }
#pragma unroll
    for (int o = 16; o; o >>= 1) acc += __shfl_xor_sync(0xffffffffu, acc, o);
    if (lane == 0) g_w2eff[w] = acc;
}

// ---------------------------------------------------------------------------
// Prep 2: scalar constant
// ---------------------------------------------------------------------------
__global__ void prep_const(const float* __restrict__ Lb1,
                           const float* __restrict__ g1,
                           const float* __restrict__ be1,
                           const float* __restrict__ Lb2,
                           const float* __restrict__ g2,
                           const float* __restrict__ be2) {
    const float inv = rsqrtf(1.f + 1e-5f);
    int k = threadIdx.x;
    float w2e = g_w2eff[k];
    float v = inv * inv * g1[k] * w2e * Lb1[k] + inv * be1[k] * w2e;
    if (k < H2) v += inv * g2[k] * Lb2[k] + be2[k];
    __shared__ float sh[H1];
    sh[k] = v;
    __syncthreads();
    for (int s = H1 / 2; s; s >>= 1) {
        if (k < s) sh[k] += sh[k + s];
        __syncthreads();
    }
    if (k == 0) g_CONST = sh[0];
}

// ---------------------------------------------------------------------------
// Prep 3: w1eff[d] = sum_k Lw1[d,k] * g1[k] * w2eff[k]
// ---------------------------------------------------------------------------
__global__ void prep_w1eff(const float* __restrict__ Lw1,
                           const float* __restrict__ g1) {
    int w    = (blockIdx.x * blockDim.x + threadIdx.x) >> 5;
    int lane = threadIdx.x & 31;
    if (w >= D_IN) return;
    float acc = 0.f;
#pragma unroll
    for (int i = 0; i < H1 / 32; i++) {
        int k = lane + i * 32;
        acc = fmaf(__ldg(Lw1 + w * H1 + k), __ldg(g1 + k) * g_w2eff[k], acc);
    }
#pragma unroll
    for (int o = 16; o; o >>= 1) acc += __shfl_xor_sync(0xffffffffu, acc, o);
    if (lane == 0) g_w1eff[w] = acc;
}

// ---------------------------------------------------------------------------
// Main kernel: ONE WARP PER SAMPLE.
//   lanes 0-15  : table 1 (emb1/W1/b1), e = lane        -> fm_first path
//   lanes 16-31 : table 2 (emb2/W2/b2), e = lane - 16   -> FM-2nd + MLP path
// Every LDG fetches both tables' rows for a slot (two 64B lines per request).
// 2048 blocks x 256 threads = 524K threads chip-wide.
// ---------------------------------------------------------------------------

// Gather + consume CH sparse slots starting at c0 (loads batched first).
template <int CH>
__device__ __forceinline__ void sparse_chunk(
    int c0, const int* xi, const float* xv, int e,
    const float* __restrict__ Etab, const float* sh_w1e,
    float& acc1, float& se, float& ss, float& hd)
{
    float a[CH], vv[CH];
    int   off[CH];
#pragma unroll
    for (int j = 0; j < CH; j++) {
        int s  = c0 + j;
        int id = xi[F_DENSE + s];
        vv[j]  = xv[F_DENSE + s];
        off[j] = (s * VOC + id) * E_DIM + e;
    }
#pragma unroll
    for (int j = 0; j < CH; j++) a[j] = __ldg(Etab + off[j]);
#pragma unroll
    for (int j = 0; j < CH; j++) {
        int s = c0 + j;
        float sev = a[j] * vv[j];
        acc1 = fmaf(a[j], vv[j], acc1);
        se  += sev;
        ss   = fmaf(sev, sev, ss);
        hd   = fmaf(sev, sh_w1e[(F_DENSE + s) * E_DIM + e], hd);
    }
}

__global__ __launch_bounds__(THREADS) void deepfm_main(
    const int*   __restrict__ Xi,
    const float* __restrict__ Xv,
    const float* __restrict__ W1,
    const float* __restrict__ b1,
    const float* __restrict__ emb1,
    const float* __restrict__ W2,
    const float* __restrict__ b2,
    const float* __restrict__ emb2,
    const float* __restrict__ bias,
    float*       __restrict__ out,
    int n) {
    const float inv2 = 1.f / (1.f + 1e-5f);   // inv^2 = 1/(1+eps)

    __shared__ int   sh_xi[SMP_PER_BLOCK * NF];
    __shared__ float sh_xv[SMP_PER_BLOCK * NF];
    __shared__ float sh_w1e[D_IN];

    int tid  = threadIdx.x;
    int base = blockIdx.x * SMP_PER_BLOCK;

    // Stage Xi/Xv tile + w1eff (coalesced)
    {
        int tile = SMP_PER_BLOCK * NF;
        int gmax = n * NF - base * NF;
        for (int i = tid; i < tile; i += THREADS) {
            if (i < gmax) {
                sh_xi[i] = Xi[base * NF + i];
                sh_xv[i] = Xv[base * NF + i];
            }
        }
        for (int i = tid; i < D_IN; i += THREADS) sh_w1e[i] = g_w1eff[i];
    }
    __syncthreads();

    int lane = tid & 31;
    int e    = lane & 15;          // embedding column
    int tbl  = lane >> 4;          // 0: emb1/W1 path, 1: emb2/W2 path
    int warp = tid >> 5;
    int b    = base + warp;
    if (b >= n) return;

    const int*   xi = sh_xi + warp * NF;
    const float* xv = sh_xv + warp * NF;

    const float* Etab = tbl ? emb2 : emb1;
    const float* Wd   = tbl ? W2   : W1;
    const float* bd   = tbl ? b2   : b1;

    float acc1 = 0.f;   // fm_first partial   (valid on tbl==0 lanes)
    float se   = 0.f;   // sum_emb[e]         (valid on tbl==1 lanes)
    float ss   = 0.f;   // sumsq[e]           (valid on tbl==1 lanes)
    float hd   = 0.f;   // h . w1eff          (valid on tbl==1 lanes)

    // Sparse gathers (DRAM-bound part), batched
    sparse_chunk<9>( 0, xi, xv, e, Etab, sh_w1e, acc1, se, ss, hd);
    sparse_chunk<9>( 9, xi, xv, e, Etab, sh_w1e, acc1, se, ss, hd);
    sparse_chunk<8>(18, xi, xv, e, Etab, sh_w1e, acc1, se, ss, hd);

    // Dense features (params L1/L2-resident)
#pragma unroll
    for (int f = 0; f < F_DENSE; f++) {
        float x = (float)xi[f];
        float v = xv[f];
        int   o = f * E_DIM + e;
        float t = fmaf(x, __ldg(Wd + o), __ldg(bd + o));
        acc1 = fmaf(t, v, acc1);              // first_lin * xv  (tbl0)
        se  += t;                             // sec_lin         (tbl1)
        ss   = fmaf(t, t, ss);
        hd   = fmaf(t, sh_w1e[o], hd);
    }

    // Per-lane contribution: table-1 lanes carry fm_first,
    // table-2 lanes carry fm_second + collapsed-MLP. (per-e exact)
    float r = tbl ? (0.5f * (se * se - ss) + inv2 * hd) : acc1;

    // Full-warp fold (sums both halves)
#pragma unroll
    for (int o = 16; o; o >>= 1) r += __shfl_xor_sync(0xffffffffu, r, o);

    if (lane == 0) out[b] = r + g_CONST + __ldg(bias + b);
}

// ---------------------------------------------------------------------------
extern "C" void kernel_launch(void* const* d_in, const int* in_sizes, int n_in,
                              void* d_out, int out_size) {
    const int*   Xi   = (const int*)  d_in[0];
    const float* Xv   = (const float*)d_in[1];
    const float* W1   = (const float*)d_in[2];
    const float* b1   = (const float*)d_in[3];
    const float* emb1 = (const float*)d_in[4];
    const float* W2   = (const float*)d_in[5];
    const float* b2   = (const float*)d_in[6];
    const float* emb2 = (const float*)d_in[7];
    const float* Lw1  = (const float*)d_in[8];
    const float* Lb1  = (const float*)d_in[9];
    const float* g1   = (const float*)d_in[10];
    const float* be1  = (const float*)d_in[11];
    const float* Lw2  = (const float*)d_in[12];
    const float* Lb2  = (const float*)d_in[13];
    const float* g2   = (const float*)d_in[14];
    const float* be2  = (const float*)d_in[15];
    const float* bias = (const float*)d_in[16];
    float* out = (float*)d_out;

    prep_w2eff<<<(H1 * 32 + 255) / 256, 256>>>(Lw2, g2);
    prep_const<<<1, H1>>>(Lb1, g1, be1, Lb2, g2, be2);
    prep_w1eff<<<(D_IN * 32 + 255) / 256, 256>>>(Lw1, g1);

    int n = out_size;
    int blocks = (n + SMP_PER_BLOCK - 1) / SMP_PER_BLOCK;
    deepfm_main<<<blocks, THREADS>>>(Xi, Xv, W1, b1, emb1, W2, b2, emb2,
                                     bias, out, n);
}